// round 12
// baseline (speedup 1.0000x reference)
#include <cuda_runtime.h>
#include <cuda_bf16.h>
#include <math.h>
#include <stdint.h>

#define Bb 16
#define Cc 32
#define Hh 128
#define Ww 128
#define HW 16384
#define Rr 8
#define OUTC 32

typedef unsigned long long ull;

// ---------------- scratch (device globals; no allocation) ----------------
__device__ __align__(16) float d_kern[Bb * Rr * 288 * 32];   // [b][r][c*9+kl][oo]
__device__ float          d_pool[Bb * Cc * 9];               // [b][c][kl]
__device__ float          d_gate[Bb * 576];                  // [b][rr*9+kl]
__device__ unsigned char  d_sel[Bb * HW];                    // r1 | r2<<3
__device__ int            d_segcnt[Bb * Rr * 64];
__device__ int            d_segbase[Bb * Rr * 64];
__device__ int            d_cnt[Bb * Rr];
__device__ unsigned short d_list[Bb * Rr * HW];              // pix | flags<<14 (sorted by pix)
__device__ __align__(16) float d_cat[(size_t)Bb * HW * 64];  // PIXEL-MAJOR [b][pix][ch] (spa 0-31, spec 32-63)
__device__ __align__(16) unsigned short d_wfbh[9 * 32 * 64]; // bf16 hi [tap][oo][ch]
__device__ __align__(16) unsigned short d_wfbl[9 * 32 * 64]; // bf16 lo [tap][oo][ch]

// ---------------- f32x2 / bit helpers ----------------
__device__ __forceinline__ ull pack2(float v) {
    ull r; asm("mov.b64 %0, {%1, %1};" : "=l"(r) : "f"(v)); return r;
}
__device__ __forceinline__ ull ffma2(ull a, ull b, ull c) {
    ull d; asm("fma.rn.f32x2 %0, %1, %2, %3;" : "=l"(d) : "l"(a), "l"(b), "l"(c)); return d;
}
__device__ __forceinline__ uint32_t prmt7632(uint32_t a, uint32_t b) {
    uint32_t r; asm("prmt.b32 %0, %1, %2, 0x7632;" : "=r"(r) : "r"(a), "r"(b)); return r;
}
__device__ __forceinline__ uint32_t smem_u32(const void* p) {
    uint32_t a;
    asm("{ .reg .u64 t; cvta.to.shared.u64 t, %1; cvt.u32.u64 %0, t; }" : "=r"(a) : "l"(p));
    return a;
}
#define LDSM4(r0, r1, r2, r3, addr) \
    asm volatile("ldmatrix.sync.aligned.m8n8.x4.shared.b16 {%0,%1,%2,%3}, [%4];" \
                 : "=r"(r0), "=r"(r1), "=r"(r2), "=r"(r3) : "r"(addr))
#define MMA16816(c, a0, a1, a2, a3, b0, b1) \
    asm volatile("mma.sync.aligned.m16n8k16.row.col.f32.bf16.bf16.f32 " \
                 "{%0,%1,%2,%3},{%4,%5,%6,%7},{%8,%9},{%0,%1,%2,%3};" \
                 : "+f"((c)[0]), "+f"((c)[1]), "+f"((c)[2]), "+f"((c)[3]) \
                 : "r"(a0), "r"(a1), "r"(a2), "r"(a3), "r"(b0), "r"(b1))

// ================= L1: pool (2 images/block) | s1 select | wf bf16-split =================
#define L1_POOL 256
#define L1_S1   1024
#define L1_WFT  72

__global__ void __launch_bounds__(256) l1_kernel(
    const float* __restrict__ in, const float* __restrict__ guide,
    const float* __restrict__ w_spa, const float* __restrict__ b_spa,
    const float* __restrict__ w_spec, const float* __restrict__ b_spec,
    const float* __restrict__ w_f) {
    int blk = blockIdx.x, t = threadIdx.x;
    __shared__ float srow[2][3][128];
    __shared__ int scnt[Rr];

    if (blk < L1_POOL) {
        int half = t >> 7, x = t & 127;
        int bc = blk * 2 + half;
        const float* img = in + (size_t)bc * HW;
        float rb0 = 0.f, rb1 = 0.f, rb2 = 0.f;
        #pragma unroll 4
        for (int yy = 0; yy < Hh; yy++) {
            float v = __ldg(img + yy * Ww + x);
            if (yy < 43) rb0 += v;
            if (yy >= 42 && yy < 86) rb1 += v;
            if (yy >= 85) rb2 += v;
        }
        srow[half][0][x] = rb0; srow[half][1][x] = rb1; srow[half][2][x] = rb2;
        __syncthreads();
        if (t < 18) {
            int h2 = t / 9, k = t % 9;
            int i = k / 3, j = k % 3;
            const int s[3] = {0, 42, 85}, e[3] = {43, 86, 128};
            const int span[3] = {43, 44, 43};
            float ssum = 0.f;
            for (int xx = s[j]; xx < e[j]; xx++) ssum += srow[h2][i][xx];
            d_pool[(blk * 2 + h2) * 9 + k] = ssum / (float)(span[i] * span[j]);
        }
    } else if (blk < L1_POOL + L1_S1) {
        int sb = blk - L1_POOL;
        int seg = sb & 63, b = sb >> 6;
        int pix = seg * 256 + t;

        float gv[Cc];
        #pragma unroll
        for (int c = 0; c < Cc; c++)
            gv[c] = __ldg(guide + ((size_t)(b * Cc + c)) * HW + pix);

        float best1 = -1e30f, best2 = -1e30f;
        int r1 = 0, r2 = 0;
        for (int r = 0; r < Rr; r++) {
            float s1 = __ldg(b_spa + r), s2 = __ldg(b_spec + r);
            #pragma unroll
            for (int c = 0; c < Cc; c++) {
                s1 += gv[c] * __ldg(w_spa + r * Cc + c);
                s2 += gv[c] * __ldg(w_spec + r * Cc + c);
            }
            if (s1 > best1) { best1 = s1; r1 = r; }
            if (s2 > best2) { best2 = s2; r2 = r; }
        }
        d_sel[b * HW + pix] = (unsigned char)(r1 | (r2 << 3));

        if (t < Rr) scnt[t] = 0;
        __syncthreads();
        if (r1 == r2) atomicAdd(&scnt[r1], 1);
        else { atomicAdd(&scnt[r1], 1); atomicAdd(&scnt[r2], 1); }
        __syncthreads();
        if (t < Rr) d_segcnt[(b * Rr + t) * 64 + seg] = scnt[t];
    } else {
        // fusion weights -> bf16 truncation split, layout [tap][oo][ch]
        int idx = (blk - L1_POOL - L1_S1) * 256 + t;
        int ch = idx & 63, o = (idx >> 6) & 31, tap = idx >> 11;
        float v = w_f[(o * 64 + ch) * 9 + tap];
        uint32_t uv = __float_as_uint(v);
        uint32_t hv = uv & 0xFFFF0000u;
        float lo = v - __uint_as_float(hv);
        d_wfbh[idx] = (unsigned short)(hv >> 16);
        __nv_bfloat16 lb = __float2bfloat16(lo);
        d_wfbl[idx] = *reinterpret_cast<unsigned short*>(&lb);
    }
}

// ================= L2: gate (16 blocks) | s2 scan (1 block) =================
__global__ void __launch_bounds__(256) l2_kernel(
    const float* __restrict__ w1, const float* __restrict__ b1) {
    int blk = blockIdx.x, t = threadIdx.x;
    if (blk < Bb) {
        int b = blk;
        for (int i = t; i < 576; i += 256) {
            int rr = i / 9, kl = i % 9;
            float s = __ldg(b1 + rr);
            #pragma unroll
            for (int c = 0; c < Cc; c++)
                s += d_pool[(b * Cc + c) * 9 + kl] * __ldg(w1 + rr * Cc + c);
            d_gate[b * 576 + i] = 1.f / (1.f + expf(-s));
        }
    } else {
        if (t < Bb * Rr) {
            int s = 0;
            for (int seg = 0; seg < 64; seg++) {
                d_segbase[t * 64 + seg] = s;
                s += d_segcnt[t * 64 + seg];
            }
            d_cnt[t] = s;
        }
    }
}

// ================= L3: kern gen (4608 blocks) | s3 emit (1024 blocks) =================
#define L3_KERN 4608

__global__ void __launch_bounds__(256) l3_kernel(
    const float* __restrict__ w2, const float* __restrict__ b2) {
    int blk = blockIdx.x, t = threadIdx.x;
    __shared__ int wcnt[8][8];

    if (blk < L3_KERN) {
        int idx = blk * 256 + t;
        int oo = idx & 31;
        int ckl = (idx >> 5) % 288;
        int t2 = idx / (288 * 32);
        int r = t2 & 7;
        int b = t2 >> 3;
        int c = ckl / 9, kl = ckl % 9;
        int jj = r * 1024 + oo * 32 + c;
        float v = __ldg(b2 + jj);
        float4 wa = __ldg((const float4*)(w2 + jj * 8));
        float4 wb = __ldg((const float4*)(w2 + jj * 8 + 4));
        const float* gb = d_gate + b * 576 + r * 72 + kl;
        v += gb[0]  * wa.x + gb[9]  * wa.y + gb[18] * wa.z + gb[27] * wa.w;
        v += gb[36] * wb.x + gb[45] * wb.y + gb[54] * wb.z + gb[63] * wb.w;
        d_kern[idx] = v;
    } else {
        int sb = blk - L3_KERN;
        int seg = sb & 63, b = sb >> 6;
        int w = t >> 5, lane = t & 31;
        int pix = seg * 256 + t;
        int sel = d_sel[b * HW + pix];
        int r1 = sel & 7, r2 = sel >> 3;

        int rank1 = 0, rank2 = 0;
        unsigned ltm = (1u << lane) - 1u;
        #pragma unroll
        for (int r = 0; r < Rr; r++) {
            unsigned m = __ballot_sync(0xFFFFFFFFu, (r1 == r) || (r2 == r));
            if (lane == 0) wcnt[w][r] = __popc(m);
            if (r1 == r) rank1 = __popc(m & ltm);
            if (r2 == r) rank2 = __popc(m & ltm);
        }
        __syncthreads();
        int wb1 = 0, wb2 = 0;
        for (int w2i = 0; w2i < w; w2i++) { wb1 += wcnt[w2i][r1]; wb2 += wcnt[w2i][r2]; }

        unsigned short pv = (unsigned short)pix;
        if (r1 == r2) {
            int off = d_segbase[(b * Rr + r1) * 64 + seg] + wb1 + rank1;
            d_list[(b * Rr + r1) * HW + off] = (unsigned short)(pv | (3u << 14));
        } else {
            int off1 = d_segbase[(b * Rr + r1) * 64 + seg] + wb1 + rank1;
            d_list[(b * Rr + r1) * HW + off1] = (unsigned short)(pv | (1u << 14));
            int off2 = d_segbase[(b * Rr + r2) * 64 + seg] + wb2 + rank2;
            d_list[(b * Rr + r2) * HW + off2] = (unsigned short)(pv | (2u << 14));
        }
    }
}

// ================= L4: dynconv v5 — lane = (oo-half, entry), 4 entry-streams =================
// grid (32, 8, 16), block 256 (8 warps). Warp: 4 streams x 16 entries = 64; block = 512.
__global__ void __launch_bounds__(256, 2) dynconv_kernel(const float* __restrict__ in) {
    int b = blockIdx.z, r = blockIdx.y;
    int cnt = d_cnt[b * Rr + r];
    int base = blockIdx.x * 512;
    if (base >= cnt) return;

    __shared__ __align__(16) float ks[288 * 32];   // [c*9+tap][oo]
    {
        const float4* kg = (const float4*)(d_kern + (size_t)(b * Rr + r) * 9216);
        float4* kd = (float4*)ks;
        #pragma unroll
        for (int i = 0; i < 9; i++) kd[threadIdx.x + 256 * i] = kg[threadIdx.x + 256 * i];
    }
    __syncthreads();

    int w = threadIdx.x >> 5, lane = threadIdx.x & 31;
    int h = lane >> 4, q = lane & 15;          // h = oo half, q = entry slot
    const unsigned short* lst = d_list + (b * Rr + r) * HW;
    const float* inb = in + (size_t)b * Cc * HW;

    int pix[4], fl[4];
    unsigned vm[4];
    #pragma unroll
    for (int s = 0; s < 4; s++) {
        int e = base + w * 64 + s * 16 + q;
        int ent = (e < cnt) ? (int)lst[e] : 0;
        fl[s] = (e < cnt) ? (ent >> 14) : 0;
        pix[s] = ent & 0x3FFF;
        int y = pix[s] >> 7, x = pix[s] & 127;
        unsigned m = 0;
        #pragma unroll
        for (int tap = 0; tap < 9; tap++) {
            int ky = tap / 3, kx = tap % 3;
            if ((unsigned)(y + ky - 1) < 128u && (unsigned)(x + kx - 1) < 128u) m |= 1u << tap;
        }
        vm[s] = fl[s] ? m : 0;
    }

    const int DOFF[9] = {-Ww - 1, -Ww, -Ww + 1, -1, 0, 1, Ww - 1, Ww, Ww + 1};

    ull acc[4][8];
    #pragma unroll
    for (int s = 0; s < 4; s++)
        #pragma unroll
        for (int u = 0; u < 8; u++) acc[s][u] = 0;

    for (int c = 0; c < Cc; c++) {
        const float* inc = inb + (size_t)c * HW;
        const float* kc = ks + c * 288 + h * 16;   // this half's 16 oo
        #pragma unroll
        for (int tap = 0; tap < 9; tap++) {
            const ulonglong2* wp = (const ulonglong2*)(kc + tap * 32);
            ulonglong2 wA = wp[0], wB = wp[1], wC = wp[2], wD = wp[3];
            #pragma unroll
            for (int s = 0; s < 4; s++) {
                float v = (vm[s] >> tap & 1) ? __ldg(inc + pix[s] + DOFF[tap]) : 0.f;
                ull a = pack2(v);
                acc[s][0] = ffma2(a, wA.x, acc[s][0]);
                acc[s][1] = ffma2(a, wA.y, acc[s][1]);
                acc[s][2] = ffma2(a, wB.x, acc[s][2]);
                acc[s][3] = ffma2(a, wB.y, acc[s][3]);
                acc[s][4] = ffma2(a, wC.x, acc[s][4]);
                acc[s][5] = ffma2(a, wC.y, acc[s][5]);
                acc[s][6] = ffma2(a, wD.x, acc[s][6]);
                acc[s][7] = ffma2(a, wD.y, acc[s][7]);
            }
        }
    }

    float* catb = d_cat + (size_t)b * HW * 64;
    #pragma unroll
    for (int s = 0; s < 4; s++) {
        const float* af = (const float*)acc[s];
        float* cp = catb + (size_t)pix[s] * 64 + h * 16;
        if (fl[s] & 1) {
            #pragma unroll
            for (int u = 0; u < 4; u++)
                ((float4*)cp)[u] = make_float4(af[4*u], af[4*u+1], af[4*u+2], af[4*u+3]);
        }
        if (fl[s] & 2) {
            #pragma unroll
            for (int u = 0; u < 4; u++)
                ((float4*)(cp + 32))[u] = make_float4(af[4*u], af[4*u+1], af[4*u+2], af[4*u+3]);
        }
    }
}

// ================= L5: fusion via mma.sync bf16 (3-product split) — unchanged =================
#define FA_BYTES 16640
#define FB_BYTES 4096
#define F_SMEM (2 * FA_BYTES + 2 * FB_BYTES)   // 41472

__global__ void __launch_bounds__(256) fusion_mma_kernel(
    const float* __restrict__ in, const float* __restrict__ b_f,
    float* __restrict__ out) {
    extern __shared__ __align__(16) char sm[];
    char* Ah = sm;
    char* Al = sm + FA_BYTES;
    char* Bh = sm + 2 * FA_BYTES;
    char* Bl = sm + 2 * FA_BYTES + FB_BYTES;
    uint32_t AhA = smem_u32(Ah), AlA = smem_u32(Al);
    uint32_t BhA = smem_u32(Bh), BlA = smem_u32(Bl);

    int tid = threadIdx.x, wid = tid >> 5, l = tid & 31;
    int g = l >> 2, tq = l & 3;
    int y = blockIdx.x, b = blockIdx.y;
    const float* catb = d_cat + (size_t)b * HW * 64;

    float acc[4][4];
    #pragma unroll
    for (int nt = 0; nt < 4; nt++)
        #pragma unroll
        for (int i = 0; i < 4; i++) acc[nt][i] = 0.f;

    for (int ky = 0; ky < 3; ky++) {
        int yy = y + ky - 1;
        if ((unsigned)yy >= 128u) continue;
        __syncthreads();
        // ---- stage A: rows rr=0..129 (sx=rr-1), 64 ch, hi/lo bf16, swizzled ----
        {
            const float4* srcb = (const float4*)(catb + ((size_t)yy * 128 - 1) * 64);
            #pragma unroll
            for (int i = 0; i < 9; i++) {
                int f = i * 256 + tid;
                if (f < 2080) {
                    int rr = f >> 4, c4 = f & 15;
                    int sx = rr - 1;
                    float4 v = make_float4(0.f, 0.f, 0.f, 0.f);
                    if ((unsigned)sx < 128u) v = __ldg(srcb + f);
                    uint32_t hx = prmt7632(__float_as_uint(v.x), __float_as_uint(v.y));
                    uint32_t hz = prmt7632(__float_as_uint(v.z), __float_as_uint(v.w));
                    float lx = v.x - __uint_as_float(__float_as_uint(v.x) & 0xFFFF0000u);
                    float ly = v.y - __uint_as_float(__float_as_uint(v.y) & 0xFFFF0000u);
                    float lz = v.z - __uint_as_float(__float_as_uint(v.z) & 0xFFFF0000u);
                    float lw = v.w - __uint_as_float(__float_as_uint(v.w) & 0xFFFF0000u);
                    __nv_bfloat162 p0 = __floats2bfloat162_rn(lx, ly);
                    __nv_bfloat162 p1 = __floats2bfloat162_rn(lz, lw);
                    uint32_t off = rr * 128 + ((((c4 >> 1)) ^ (rr & 7)) << 4) + (c4 & 1) * 8;
                    *(uint2*)(Ah + off) = make_uint2(hx, hz);
                    *(uint2*)(Al + off) = make_uint2(*(uint32_t*)&p0, *(uint32_t*)&p1);
                }
            }
        }
        for (int kx = 0; kx < 3; kx++) {
            int tap = ky * 3 + kx;
            __syncthreads();
            // ---- stage B[tap]: [oo][ch] bf16 hi/lo, swizzled ----
            {
                int oo = tid >> 3, u = tid & 7;
                uint4 sh = ((const uint4*)d_wfbh)[tap * 256 + tid];
                uint4 sl = ((const uint4*)d_wfbl)[tap * 256 + tid];
                uint32_t off = oo * 128 + ((u ^ (oo & 7)) << 4);
                *(uint4*)(Bh + off) = sh;
                *(uint4*)(Bl + off) = sl;
            }
            __syncthreads();

            int rra = wid * 16 + (l & 15) + kx;     // 0..129
            int kha = l >> 4;
            int nn = ((l >> 4) & 1) * 8 + (l & 7);
            int khb = (l >> 3) & 1;

            #pragma unroll
            for (int kc = 0; kc < 4; kc++) {
                uint32_t ua = (uint32_t)(kc * 2 + kha);
                uint32_t aoff = rra * 128 + ((ua ^ (rra & 7)) << 4);
                uint32_t ah0, ah1, ah2, ah3, al0, al1, al2, al3;
                LDSM4(ah0, ah1, ah2, ah3, AhA + aoff);
                LDSM4(al0, al1, al2, al3, AlA + aoff);

                uint32_t ub = (uint32_t)(kc * 2 + khb);
                uint32_t boff1 = nn * 128 + ((ub ^ (nn & 7)) << 4);
                uint32_t boff2 = (nn + 16) * 128 + ((ub ^ ((nn + 16) & 7)) << 4);
                uint32_t bh0, bh1, bh2, bh3, bh4, bh5, bh6, bh7;
                uint32_t bl0, bl1, bl2, bl3, bl4, bl5, bl6, bl7;
                LDSM4(bh0, bh1, bh2, bh3, BhA + boff1);
                LDSM4(bh4, bh5, bh6, bh7, BhA + boff2);
                LDSM4(bl0, bl1, bl2, bl3, BlA + boff1);
                LDSM4(bl4, bl5, bl6, bl7, BlA + boff2);

                MMA16816(acc[0], ah0, ah1, ah2, ah3, bh0, bh1);
                MMA16816(acc[1], ah0, ah1, ah2, ah3, bh2, bh3);
                MMA16816(acc[2], ah0, ah1, ah2, ah3, bh4, bh5);
                MMA16816(acc[3], ah0, ah1, ah2, ah3, bh6, bh7);
                MMA16816(acc[0], ah0, ah1, ah2, ah3, bl0, bl1);
                MMA16816(acc[1], ah0, ah1, ah2, ah3, bl2, bl3);
                MMA16816(acc[2], ah0, ah1, ah2, ah3, bl4, bl5);
                MMA16816(acc[3], ah0, ah1, ah2, ah3, bl6, bl7);
                MMA16816(acc[0], al0, al1, al2, al3, bh0, bh1);
                MMA16816(acc[1], al0, al1, al2, al3, bh2, bh3);
                MMA16816(acc[2], al0, al1, al2, al3, bh4, bh5);
                MMA16816(acc[3], al0, al1, al2, al3, bh6, bh7);
            }
        }
    }

    int px0 = wid * 16 + g;
    size_t rowoff = (size_t)y * Ww;
    #pragma unroll
    for (int nt = 0; nt < 4; nt++) {
        int o0 = nt * 8 + tq * 2;
        float bi0 = __ldg(b_f + o0), bi1 = __ldg(b_f + o0 + 1);
        size_t i00 = ((size_t)(b * OUTC + o0)) * HW + rowoff + px0;
        size_t i01 = ((size_t)(b * OUTC + o0 + 1)) * HW + rowoff + px0;
        out[i00]     = acc[nt][0] + bi0 + __ldg(in + i00);
        out[i01]     = acc[nt][1] + bi1 + __ldg(in + i01);
        out[i00 + 8] = acc[nt][2] + bi0 + __ldg(in + i00 + 8);
        out[i01 + 8] = acc[nt][3] + bi1 + __ldg(in + i01 + 8);
    }
}

// ---------------- launch ----------------
extern "C" void kernel_launch(void* const* d_in, const int* in_sizes, int n_in,
                              void* d_out, int out_size) {
    const float* input  = (const float*)d_in[0];
    const float* guide  = (const float*)d_in[1];
    const float* w1     = (const float*)d_in[2];
    const float* b1     = (const float*)d_in[3];
    const float* w2     = (const float*)d_in[4];
    const float* b2     = (const float*)d_in[5];
    const float* w_spa  = (const float*)d_in[6];
    const float* b_spa  = (const float*)d_in[7];
    const float* w_spec = (const float*)d_in[8];
    const float* b_spec = (const float*)d_in[9];
    const float* w_f    = (const float*)d_in[10];
    const float* b_f    = (const float*)d_in[11];
    float* out = (float*)d_out;

    l1_kernel<<<L1_POOL + L1_S1 + L1_WFT, 256>>>(input, guide, w_spa, b_spa, w_spec, b_spec, w_f);
    l2_kernel<<<Bb + 1, 256>>>(w1, b1);
    l3_kernel<<<L3_KERN + 1024, 256>>>(w2, b2);
    dynconv_kernel<<<dim3(32, Rr, Bb), 256>>>(input);
    fusion_mma_kernel<<<dim3(Hh, Bb), 256, F_SMEM>>>(input, b_f, out);
}